// round 2
// baseline (speedup 1.0000x reference)
#include <cuda_runtime.h>
#include <stdint.h>

// RasterTriangle_46566035423850
// out[b, img, p, q]:
//   img=0 (hf): sum_{k<64} vert_hf(p,k) * hor_hf(q,k) / AREA
//   img=1 (ri): sum_{k<32} vert_ri(p,k) * hor_ri(q,k) / AREA
// Key idea: per k, hor(.,k) along q is piecewise-constant except at <=~6 samples
// (ramps span exactly one pixel). So the per-row result is the prefix sum of a
// sparse row-difference vector: out[p,:] = prefix_q( sum_k v(p,k) * dH_k ).

#define NTHREADS 256
#define NW 8          // warps per CTA
#define CAP 2048      // max diff entries per image (actual <= ~512)

__global__ void __launch_bounds__(NTHREADS)
raster_kernel(const float* __restrict__ iv0,
              const float* __restrict__ iv1,
              float* __restrict__ out)
{
    // ---- constants, replicating the reference fp32 semantics ----
    const double PI_D   = 3.141592653589793238462643383279502884;
    const double SIDE_D = (PI_D * 0.5) / 512.0;
    const float  S      = (float)SIDE_D;                 // SIDE
    const float  STRIPF = (float)(PI_D * 0.5);           // STRIP
    const float  STOPF  = (float)(PI_D * 0.5 - SIDE_D);  // R_MAX - SIDE
    const float  stepx  = __fdiv_rn(STOPF, 511.0f);      // linspace step for PX
    const float  stepy  = __fdiv_rn(-STOPF, 511.0f);     // linspace step for PY
    const float  invA   = (float)(1.0 / (SIDE_D * SIDE_D));

    __shared__ __align__(16) float xs[64], ys[64];
    __shared__ __align__(16) uint2 entries[CAP];
    __shared__ __align__(16) unsigned short cnt[64][32];  // per (k,bucket) counts -> excl prefix
    __shared__ __align__(16) int bcount[32];
    __shared__ __align__(16) int boff[33];
    __shared__ __align__(16) float vbuf[NW][64];
    __shared__ __align__(16) float rowbuf[NW][512];

    const int tid     = threadIdx.x;
    const int bid     = blockIdx.x;          // 0..2047
    const int imgslot = bid >> 2;            // 0..511 = b*2 + img
    const int img     = imgslot & 1;         // 0=hf, 1=ri
    const int b       = imgslot >> 1;
    const int rowstart = (bid & 3) << 7;     // 128-row quarter of the image
    const int K       = img ? 32 : 64;

    // ---- load interval endpoints into (xs, ys) per the reference's concat ----
    if (tid < 32) {
        const float2 ab = ((const float2*)iv0)[b * 32 + tid];  // (a0, b0)
        xs[tid] = ab.x;            // a0
        ys[tid] = ab.y;            // b0
    } else if (tid < 64 && img == 0) {
        const float2 ab = ((const float2*)iv1)[b * 32 + (tid - 32)];  // (a1, b1)
        xs[tid] = __fsub_rn(ab.y, STRIPF);   // b1 - STRIP
        ys[tid] = ab.x;                      // a1
    }
    __syncthreads();

    // ---- Phase 1A: count nonzero column diffs of hor(.,k) per 16-wide bucket ----
    // Tasks: (k, chunk-of-64-q). Each task owns buckets [4*chunk, 4*chunk+4) of row k
    // exclusively -> no atomics, deterministic.
    for (int task = tid; task < K * 8; task += NTHREADS) {
        const int k  = task >> 3;
        const int q0 = (task & 7) << 6;
        const float x = xs[k], y = ys[k];
        float fp;
        if (q0 == 0) {
            fp = 0.0f;
        } else {
            const float px = __fmul_rn((float)(q0 - 1), stepx);
            const float A  = __fsub_rn(__fadd_rn(px, S), x);
            const float m  = img ? A : fminf(A, __fsub_rn(y, px));
            fp = fmaxf(fminf(S, m), 0.0f);
        }
        int q = q0;
        #pragma unroll
        for (int bi = 0; bi < 4; ++bi) {
            int c = 0;
            for (int j = 0; j < 16; ++j, ++q) {
                const float px = __fmul_rn((float)q, stepx);
                const float A  = __fsub_rn(__fadd_rn(px, S), x);
                const float m  = img ? A : fminf(A, __fsub_rn(y, px));
                const float f  = fmaxf(fminf(S, m), 0.0f);
                if (f != fp) ++c;
                fp = f;
            }
            cnt[k][(q0 >> 4) + bi] = (unsigned short)c;
        }
    }
    __syncthreads();

    // exclusive prefix over k within each bucket; bucket totals
    if (tid < 32) {
        int s = 0;
        for (int k = 0; k < K; ++k) {
            const int t = cnt[k][tid];
            cnt[k][tid] = (unsigned short)s;
            s += t;
        }
        bcount[tid] = s;
    }
    __syncthreads();
    if (tid == 0) {
        int s = 0;
        #pragma unroll
        for (int i = 0; i < 32; ++i) { boff[i] = s; s += bcount[i]; }
        boff[32] = s;
    }
    __syncthreads();

    // ---- Phase 1B: emit entries at deterministic slots ----
    for (int task = tid; task < K * 8; task += NTHREADS) {
        const int k  = task >> 3;
        const int q0 = (task & 7) << 6;
        const float x = xs[k], y = ys[k];
        float fp;
        if (q0 == 0) {
            fp = 0.0f;
        } else {
            const float px = __fmul_rn((float)(q0 - 1), stepx);
            const float A  = __fsub_rn(__fadd_rn(px, S), x);
            const float m  = img ? A : fminf(A, __fsub_rn(y, px));
            fp = fmaxf(fminf(S, m), 0.0f);
        }
        int q = q0;
        #pragma unroll
        for (int bi = 0; bi < 4; ++bi) {
            const int bk = (q0 >> 4) + bi;
            int pos = boff[bk] + (int)cnt[k][bk];
            for (int j = 0; j < 16; ++j, ++q) {
                const float px = __fmul_rn((float)q, stepx);
                const float A  = __fsub_rn(__fadd_rn(px, S), x);
                const float m  = img ? A : fminf(A, __fsub_rn(y, px));
                const float f  = fmaxf(fminf(S, m), 0.0f);
                if (f != fp) {
                    if (pos < CAP)
                        entries[pos] = make_uint2(((unsigned)k << 16) | (unsigned)q,
                                                  __float_as_uint(__fsub_rn(f, fp)));
                    ++pos;
                }
                fp = f;
            }
        }
    }
    __syncthreads();

    // ---- Phase 2: one warp per row; scatter + scan + coalesced store ----
    const int warp = tid >> 5;
    const int lane = tid & 31;
    float4* const rb4 = (float4*)rowbuf[warp];
    float*  const vb  = vbuf[warp];
    const int e0 = boff[lane];
    const int e1 = boff[lane + 1];

    for (int pr = 0; pr < 16; ++pr) {
        const int p = rowstart + (pr << 3) + warp;

        // vert(p,k) * (1/AREA) for all k
        {
            const float py = __fadd_rn(STOPF, __fmul_rn((float)p, stepy));
            {
                const float x = xs[lane], y = ys[lane];
                float m;
                if (img) m = __fsub_rn(y, py);
                else m = fminf(__fsub_rn(__fadd_rn(py, S), y),
                               __fsub_rn(__fadd_rn(x, STRIPF), py));
                vb[lane] = fmaxf(fminf(S, m), 0.0f) * invA;
            }
            if (!img) {
                const float x = xs[lane + 32], y = ys[lane + 32];
                const float m = fminf(__fsub_rn(__fadd_rn(py, S), y),
                                      __fsub_rn(__fadd_rn(x, STRIPF), py));
                vb[lane + 32] = fmaxf(fminf(S, m), 0.0f) * invA;
            }
        }

        // zero this warp's row buffer (lane owns q in [16*lane, 16*lane+16))
        const float4 z4 = make_float4(0.f, 0.f, 0.f, 0.f);
        rb4[lane * 4 + 0] = z4;
        rb4[lane * 4 + 1] = z4;
        rb4[lane * 4 + 2] = z4;
        rb4[lane * 4 + 3] = z4;
        __syncwarp();

        // sparse scatter: row-difference vector R[q] += v[k] * dH[k][q]
        for (int e = e0; e < e1; ++e) {
            const uint2 en = entries[e];
            const int q = (int)(en.x & 0xFFFFu);
            const float v = vb[en.x >> 16];
            rowbuf[warp][q] = __fmaf_rn(v, __uint_as_float(en.y), rowbuf[warp][q]);
        }
        __syncwarp();

        // inclusive scan of 512: 16 sequential per lane + warp scan of totals
        float4 c0 = rb4[lane * 4 + 0];
        float4 c1 = rb4[lane * 4 + 1];
        float4 c2 = rb4[lane * 4 + 2];
        float4 c3 = rb4[lane * 4 + 3];
        c0.y += c0.x; c0.z += c0.y; c0.w += c0.z;
        c1.x += c0.w; c1.y += c1.x; c1.z += c1.y; c1.w += c1.z;
        c2.x += c1.w; c2.y += c2.x; c2.z += c2.y; c2.w += c2.z;
        c3.x += c2.w; c3.y += c3.x; c3.z += c3.y; c3.w += c3.z;
        const float total = c3.w;
        float incl = total;
        #pragma unroll
        for (int d = 1; d < 32; d <<= 1) {
            const float t = __shfl_up_sync(0xFFFFFFFFu, incl, d);
            if (lane >= d) incl += t;
        }
        const float excl = incl - total;
        c0.x += excl; c0.y += excl; c0.z += excl; c0.w += excl;
        c1.x += excl; c1.y += excl; c1.z += excl; c1.w += excl;
        c2.x += excl; c2.y += excl; c2.z += excl; c2.w += excl;
        c3.x += excl; c3.y += excl; c3.z += excl; c3.w += excl;

        // restage through shared so global stores are fully coalesced
        rb4[lane * 4 + 0] = c0;
        rb4[lane * 4 + 1] = c1;
        rb4[lane * 4 + 2] = c2;
        rb4[lane * 4 + 3] = c3;
        __syncwarp();

        float4* orow = (float4*)(out + ((size_t)imgslot << 18) + ((size_t)p << 9));
        orow[lane +  0] = rb4[lane +  0];
        orow[lane + 32] = rb4[lane + 32];
        orow[lane + 64] = rb4[lane + 64];
        orow[lane + 96] = rb4[lane + 96];
        __syncwarp();
    }
}

extern "C" void kernel_launch(void* const* d_in, const int* in_sizes, int n_in,
                              void* d_out, int out_size)
{
    const float* iv0 = (const float*)d_in[0];   // intervals00: (256, 32, 2) f32
    const float* iv1 = (const float*)d_in[1];   // intervals01: (256, 32, 2) f32
    float* out = (float*)d_out;                 // (256, 2, 512, 512) f32
    (void)in_sizes; (void)n_in; (void)out_size;
    raster_kernel<<<2048, NTHREADS>>>(iv0, iv1, out);
}

// round 3
// speedup vs baseline: 1.1205x; 1.1205x over previous
#include <cuda_runtime.h>
#include <stdint.h>

// RasterTriangle_46566035423850
// out[b, img, p, q]:
//   img=0 (hf): sum_{k<64} vert_hf(p,k) * hor_hf(q,k) / AREA
//   img=1 (ri): sum_{k<32} vert_ri(p,k) * hor_ri(q,k) / AREA
// Sparse row-difference + prefix-scan formulation. Per-row accumulation is done
// fully in registers (4-wide buckets, predicated adds), stores are directly
// coalesced STG.128 -- no shared row buffer at all.

#define NTHREADS 256
#define NW 8          // warps per CTA
#define CAP 2048      // max diff entries per image (actual <= ~512)

__global__ void __launch_bounds__(NTHREADS)
raster_kernel(const float* __restrict__ iv0,
              const float* __restrict__ iv1,
              float* __restrict__ out)
{
    // ---- constants, replicating the reference fp32 semantics ----
    const double PI_D   = 3.141592653589793238462643383279502884;
    const double SIDE_D = (PI_D * 0.5) / 512.0;
    const float  S      = (float)SIDE_D;                 // SIDE
    const float  STRIPF = (float)(PI_D * 0.5);           // STRIP
    const float  STOPF  = (float)(PI_D * 0.5 - SIDE_D);  // R_MAX - SIDE
    const float  stepx  = __fdiv_rn(STOPF, 511.0f);      // linspace step for PX
    const float  stepy  = __fdiv_rn(-STOPF, 511.0f);     // linspace step for PY
    const float  invA   = (float)(1.0 / (SIDE_D * SIDE_D));

    __shared__ __align__(16) float xs[64], ys[64];
    __shared__ __align__(16) uint2 entries[CAP];
    __shared__ __align__(16) unsigned short cnt[64][128]; // per (k, 4-wide bucket)
    __shared__ __align__(16) int bcount[128];
    __shared__ __align__(16) int boff[129];
    __shared__ __align__(16) float vbuf[NW][64];

    const int tid     = threadIdx.x;
    const int bid     = blockIdx.x;          // 0..2047
    const int imgslot = bid >> 2;            // 0..511 = b*2 + img
    const int img     = imgslot & 1;         // 0=hf, 1=ri
    const int b       = imgslot >> 1;
    const int rowstart = (bid & 3) << 7;     // 128-row quarter of the image
    const int K       = img ? 32 : 64;

    // ---- load interval endpoints into (xs, ys) per the reference's concat ----
    if (tid < 32) {
        const float2 ab = ((const float2*)iv0)[b * 32 + tid];  // (a0, b0)
        xs[tid] = ab.x;            // a0
        ys[tid] = ab.y;            // b0
    } else if (tid < 64 && img == 0) {
        const float2 ab = ((const float2*)iv1)[b * 32 + (tid - 32)];  // (a1, b1)
        xs[tid] = __fsub_rn(ab.y, STRIPF);   // b1 - STRIP
        ys[tid] = ab.x;                      // a1
    }
    __syncthreads();

    // ---- Phase 1A: count nonzero column diffs of hor(.,k) per 4-wide bucket ----
    for (int task = tid; task < K * 8; task += NTHREADS) {
        const int k  = task >> 3;
        const int q0 = (task & 7) << 6;
        const float x = xs[k], y = ys[k];
        float fp;
        if (q0 == 0) {
            fp = 0.0f;
        } else {
            const float px = __fmul_rn((float)(q0 - 1), stepx);
            const float A  = __fsub_rn(__fadd_rn(px, S), x);
            const float m  = img ? A : fminf(A, __fsub_rn(y, px));
            fp = fmaxf(fminf(S, m), 0.0f);
        }
        int q = q0;
        for (int bi = 0; bi < 16; ++bi) {
            int c = 0;
            #pragma unroll
            for (int j = 0; j < 4; ++j, ++q) {
                const float px = __fmul_rn((float)q, stepx);
                const float A  = __fsub_rn(__fadd_rn(px, S), x);
                const float m  = img ? A : fminf(A, __fsub_rn(y, px));
                const float f  = fmaxf(fminf(S, m), 0.0f);
                if (f != fp) ++c;
                fp = f;
            }
            cnt[k][(q0 >> 2) + bi] = (unsigned short)c;
        }
    }
    __syncthreads();

    // exclusive prefix over k within each bucket; bucket totals
    if (tid < 128) {
        int s = 0;
        for (int k = 0; k < K; ++k) {
            const int t = cnt[k][tid];
            cnt[k][tid] = (unsigned short)s;
            s += t;
        }
        bcount[tid] = s;
    }
    __syncthreads();
    if (tid == 0) {
        int s = 0;
        for (int i = 0; i < 128; ++i) { boff[i] = s; s += bcount[i]; }
        boff[128] = s;
    }
    __syncthreads();

    // ---- Phase 1B: emit entries at deterministic slots ----
    for (int task = tid; task < K * 8; task += NTHREADS) {
        const int k  = task >> 3;
        const int q0 = (task & 7) << 6;
        const float x = xs[k], y = ys[k];
        float fp;
        if (q0 == 0) {
            fp = 0.0f;
        } else {
            const float px = __fmul_rn((float)(q0 - 1), stepx);
            const float A  = __fsub_rn(__fadd_rn(px, S), x);
            const float m  = img ? A : fminf(A, __fsub_rn(y, px));
            fp = fmaxf(fminf(S, m), 0.0f);
        }
        int q = q0;
        for (int bi = 0; bi < 16; ++bi) {
            const int bk = (q0 >> 2) + bi;
            int pos = boff[bk] + (int)cnt[k][bk];
            #pragma unroll
            for (int j = 0; j < 4; ++j, ++q) {
                const float px = __fmul_rn((float)q, stepx);
                const float A  = __fsub_rn(__fadd_rn(px, S), x);
                const float m  = img ? A : fminf(A, __fsub_rn(y, px));
                const float f  = fmaxf(fminf(S, m), 0.0f);
                if (f != fp) {
                    if (pos < CAP)
                        entries[pos] = make_uint2(((unsigned)k << 16) | (unsigned)(q & 3),
                                                  __float_as_uint(__fsub_rn(f, fp)));
                    ++pos;
                }
                fp = f;
            }
        }
    }
    __syncthreads();

    // ---- Phase 2: one warp per row; register accumulation + scan + STG.128 ----
    const int warp = tid >> 5;
    const int lane = tid & 31;
    float* const vb = vbuf[warp];

    // bucket ranges for this lane's 4 q-chunks
    int es[4], ee[4];
    #pragma unroll
    for (int m = 0; m < 4; ++m) {
        const int bk = (m << 5) + lane;
        es[m] = boff[bk];
        ee[m] = boff[bk + 1];
    }

    float* const obase = out + ((size_t)imgslot << 18);

    for (int pr = 0; pr < 16; ++pr) {
        const int p = rowstart + (pr << 3) + warp;

        // vert(p,k) * (1/AREA) for all k
        {
            const float py = __fadd_rn(STOPF, __fmul_rn((float)p, stepy));
            {
                const float x = xs[lane], y = ys[lane];
                float m;
                if (img) m = __fsub_rn(y, py);
                else m = fminf(__fsub_rn(__fadd_rn(py, S), y),
                               __fsub_rn(__fadd_rn(x, STRIPF), py));
                vb[lane] = fmaxf(fminf(S, m), 0.0f) * invA;
            }
            if (!img) {
                const float x = xs[lane + 32], y = ys[lane + 32];
                const float m = fminf(__fsub_rn(__fadd_rn(py, S), y),
                                      __fsub_rn(__fadd_rn(x, STRIPF), py));
                vb[lane + 32] = fmaxf(fminf(S, m), 0.0f) * invA;
            }
        }
        __syncwarp();

        float carry = 0.0f;
        #pragma unroll
        for (int m = 0; m < 4; ++m) {
            // accumulate this lane's bucket entries into 4 registers
            float a0 = 0.f, a1 = 0.f, a2 = 0.f, a3 = 0.f;
            for (int e = es[m]; e < ee[m]; ++e) {
                const uint2 en = entries[e];
                const float vd = vb[en.x >> 16] * __uint_as_float(en.y);
                const int pos = (int)(en.x & 3u);
                a0 += (pos == 0) ? vd : 0.0f;
                a1 += (pos == 1) ? vd : 0.0f;
                a2 += (pos == 2) ? vd : 0.0f;
                a3 += (pos == 3) ? vd : 0.0f;
            }
            // in-lane prefix
            a1 += a0; a2 += a1; a3 += a2;
            // warp inclusive scan of lane totals
            const float t = a3;
            float incl = t;
            #pragma unroll
            for (int d = 1; d < 32; d <<= 1) {
                const float s = __shfl_up_sync(0xFFFFFFFFu, incl, d);
                if (lane >= d) incl += s;
            }
            const float add = incl - t + carry;   // exclusive + carry-in
            a0 += add; a1 += add; a2 += add; a3 += add;
            carry += __shfl_sync(0xFFFFFFFFu, incl, 31);

            // coalesced store: 32 lanes x 16B = 512B contiguous
            float4* dst = (float4*)(obase + ((size_t)p << 9) + (m << 7) + (lane << 2));
            *dst = make_float4(a0, a1, a2, a3);
        }
        __syncwarp();
    }
}

extern "C" void kernel_launch(void* const* d_in, const int* in_sizes, int n_in,
                              void* d_out, int out_size)
{
    const float* iv0 = (const float*)d_in[0];   // intervals00: (256, 32, 2) f32
    const float* iv1 = (const float*)d_in[1];   // intervals01: (256, 32, 2) f32
    float* out = (float*)d_out;                 // (256, 2, 512, 512) f32
    (void)in_sizes; (void)n_in; (void)out_size;
    raster_kernel<<<2048, NTHREADS>>>(iv0, iv1, out);
}

// round 5
// speedup vs baseline: 3.6190x; 3.2297x over previous
#include <cuda_runtime.h>
#include <stdint.h>

// RasterTriangle_46566035423850 — fully sparse 2D formulation.
// out[p,q] = sum_k v(p,k) * H_k[q].  Both v(.,k) over p and H(.,k) over q are
// piecewise constant except within one-pixel ramps => per-k diff lists dv (over p)
// and dh (over q) each have <= ~7 entries, found by evaluating the EXACT reference
// fp32 formula inside analytically-located windows (+/-2 sample guard).
// Per warp: base row p0 built by scatter+scan, then rows advance incrementally:
//   out[p,:] = out[p-1,:] + prefix_q( sum_{k: dv at p} dv * dH_k )   (usually zero).

#define NTHREADS 256
#define NW 8
#define MAXD 12   // max diffs per k per dim (true bound ~7)

__global__ void __launch_bounds__(NTHREADS)
raster_kernel(const float* __restrict__ iv0,
              const float* __restrict__ iv1,
              float* __restrict__ out)
{
    const double PI_D   = 3.141592653589793238462643383279502884;
    const double SIDE_D = (PI_D * 0.5) / 512.0;
    const float  S      = (float)SIDE_D;
    const float  STRIPF = (float)(PI_D * 0.5);
    const float  STOPF  = (float)(PI_D * 0.5 - SIDE_D);
    const float  stepx  = __fdiv_rn(STOPF, 511.0f);
    const float  stepy  = __fdiv_rn(-STOPF, 511.0f);
    const float  invA   = (float)(1.0 / (SIDE_D * SIDE_D));

    __shared__ __align__(16) float xs[64], ys[64];
    __shared__ __align__(16) float dhH[64][MAXD];
    __shared__ __align__(16) float dvV[64][MAXD];
    __shared__ __align__(16) short qH[64][MAXD];
    __shared__ __align__(16) short pV[64][MAXD];
    __shared__ int   cntH[64], cntV[64];
    __shared__ __align__(16) float Rbuf[NW][512];
    __shared__ __align__(16) float vbuf[NW][64];

    const int tid = threadIdx.x;
    const int bid = blockIdx.x;        // 0..511 = b*2 + img
    const int img = bid & 1;
    const int b   = bid >> 1;
    const int K   = img ? 32 : 64;

    // zero R scratch (8 warps x 512 floats)
    {
        float4* r4 = (float4*)&Rbuf[0][0];
        #pragma unroll
        for (int i = 0; i < 4; ++i)
            r4[tid * 4 + i] = make_float4(0.f, 0.f, 0.f, 0.f);
    }
    // load interval endpoints (reference's concat semantics)
    if (tid < 32) {
        const float2 ab = ((const float2*)iv0)[b * 32 + tid];
        xs[tid] = ab.x;  ys[tid] = ab.y;                 // (a0, b0)
    } else if (tid < 64 && img == 0) {
        const float2 ab = ((const float2*)iv1)[b * 32 + (tid - 32)];
        xs[tid] = __fsub_rn(ab.y, STRIPF);               // b1 - STRIP
        ys[tid] = ab.x;                                  // a1
    }
    __syncthreads();

    // ---- Phase 1: per-(k, dim) windowed diff extraction ----
    if (tid < 2 * K) {
        const int k   = tid >> 1;
        const int dim = tid & 1;     // 0 = horizontal(q), 1 = vertical(p)
        const float x = xs[k], y = ys[k];

        // analytic ramp windows (float sample coords)
        float w1lo, w1hi, w2lo, w2hi; int has2;
        if (dim == 0) {
            w1lo = __fdiv_rn(__fsub_rn(x, S), stepx);  w1hi = __fdiv_rn(x, stepx);
            w2lo = __fdiv_rn(__fsub_rn(y, S), stepx);  w2hi = __fdiv_rn(y, stepx);
            has2 = (img == 0);
        } else {
            w1lo = __fdiv_rn(__fsub_rn(STOPF, y), stepx);
            w1hi = __fdiv_rn(__fadd_rn(__fsub_rn(STOPF, y), S), stepx);
            const float t = __fsub_rn(__fsub_rn(STOPF, x), STRIPF);
            w2lo = __fdiv_rn(t, stepx);
            w2hi = __fdiv_rn(__fadd_rn(t, S), stepx);
            has2 = (img == 0);
        }

        int aLo = 0, aHi = -1, bLo = 0, bHi = -1;
        {
            const int lo = (int)floorf(w1lo) - 2, hi = (int)ceilf(w1hi) + 2;
            if (lo <= 511) { aLo = max(lo, 0); aHi = min(511, max(hi, 0)); }
        }
        if (has2) {
            const int lo = (int)floorf(w2lo) - 2, hi = (int)ceilf(w2hi) + 2;
            if (lo <= 511) { bLo = max(lo, 0); bHi = min(511, max(hi, 0)); }
        }
        if (aHi < aLo) { aLo = bLo; aHi = bHi; bHi = -1; }      // A empty -> use B
        if (bHi >= bLo) {                                        // both nonempty
            if (bLo < aLo) { int t;                              // order by lo
                t = aLo; aLo = bLo; bLo = t;  t = aHi; aHi = bHi; bHi = t; }
            if (bLo <= aHi + 1) { aHi = max(aHi, bHi); bHi = -1; }   // merge
        }

        short* qq = dim ? pV[k] : qH[k];
        float* dd = dim ? dvV[k] : dhH[k];
        int cnt = 0;
        #pragma unroll 1
        for (int sp = 0; sp < 2; ++sp) {
            const int lo = sp ? bLo : aLo, hi = sp ? bHi : aHi;
            if (hi < lo) continue;
            float prev = 0.f;
            for (int t = (lo == 0 ? 0 : lo - 1); t <= hi; ++t) {
                float f;
                if (dim == 0) {
                    const float px = __fmul_rn((float)t, stepx);
                    const float A  = __fsub_rn(__fadd_rn(px, S), x);
                    const float m  = img ? A : fminf(A, __fsub_rn(y, px));
                    f = fmaxf(fminf(S, m), 0.f);
                } else {
                    const float py = __fadd_rn(STOPF, __fmul_rn((float)t, stepy));
                    float m;
                    if (img) m = __fsub_rn(y, py);
                    else m = fminf(__fsub_rn(__fadd_rn(py, S), y),
                                   __fsub_rn(__fadd_rn(x, STRIPF), py));
                    f = fmaxf(fminf(S, m), 0.f);
                }
                if (t >= lo && f != prev && cnt < MAXD) {
                    qq[cnt] = (short)t;
                    dd[cnt] = dim ? __fmul_rn(__fsub_rn(f, prev), invA)
                                  : __fsub_rn(f, prev);
                    ++cnt;
                }
                prev = f;
            }
        }
        (dim ? cntV : cntH)[k] = cnt;
    }
    __syncthreads();

    // ---- Phase 2: per-warp segment of 64 rows ----
    const int warp = tid >> 5;
    const int lane = tid & 31;
    const int p0   = warp << 6;
    float* const R = Rbuf[warp];

    // v(p0, k) * invA  (closed form, identical ops to reference)
    {
        const float py = __fadd_rn(STOPF, __fmul_rn((float)p0, stepy));
        {
            const float x = xs[lane], y = ys[lane];
            float m;
            if (img) m = __fsub_rn(y, py);
            else m = fminf(__fsub_rn(__fadd_rn(py, S), y),
                           __fsub_rn(__fadd_rn(x, STRIPF), py));
            vbuf[warp][lane] = fmaxf(fminf(S, m), 0.f) * invA;
        }
        if (!img) {
            const float x = xs[lane + 32], y = ys[lane + 32];
            const float m = fminf(__fsub_rn(__fadd_rn(py, S), y),
                                  __fsub_rn(__fadd_rn(x, STRIPF), py));
            vbuf[warp][lane + 32] = fmaxf(fminf(S, m), 0.f) * invA;
        }
    }
    __syncwarp();

    // base row: R[q] += v(p0,k) * dh  (lane j handles entry j of k; serial over k)
    for (int k = 0; k < K; ++k) {
        const float v = vbuf[warp][k];     // broadcast
        if (v != 0.f) {
            if (lane < cntH[k]) {
                const int q = qH[k][lane];
                R[q] = __fmaf_rn(v, dhH[k][lane], R[q]);
            }
            __syncwarp();
        }
    }

    // dv cursors: lane owns k0 = lane (and k1 = lane+32 for hf)
    const int k0 = lane, k1 = lane + 32;
    const int c0 = cntV[k0];
    const int c1 = (img == 0) ? cntV[k1] : 0;
    int cur0 = 0; while (cur0 < c0 && pV[k0][cur0] <= p0) ++cur0;
    int cur1 = 0; while (cur1 < c1 && pV[k1][cur1] <= p0) ++cur1;
    int np0 = (cur0 < c0) ? pV[k0][cur0] : (1 << 30);
    int np1 = (cur1 < c1) ? pV[k1][cur1] : (1 << 30);

    float O[16];
    #pragma unroll
    for (int i = 0; i < 16; ++i) O[i] = 0.f;

    float4* orow = (float4*)(out + ((size_t)bid << 18) + ((size_t)p0 << 9));

    for (int p = p0; p < p0 + 64; ++p) {
        bool doscan = (p == p0);
        if (p > p0) {
            const bool m0 = (np0 == p), m1 = (np1 == p);
            unsigned bal0 = __ballot_sync(0xFFFFFFFFu, m0);
            unsigned bal1 = __ballot_sync(0xFFFFFFFFu, m1);
            float dv0 = 0.f, dv1 = 0.f;
            if (m0) { dv0 = dvV[k0][cur0]; ++cur0;
                      np0 = (cur0 < c0) ? pV[k0][cur0] : (1 << 30); }
            if (m1) { dv1 = dvV[k1][cur1]; ++cur1;
                      np1 = (cur1 < c1) ? pV[k1][cur1] : (1 << 30); }
            if (bal0 | bal1) {
                doscan = true;
                while (bal0) {
                    const int src = __ffs(bal0) - 1; bal0 &= bal0 - 1;
                    const float dv = __shfl_sync(0xFFFFFFFFu, dv0, src);
                    if (lane < cntH[src]) {
                        const int q = qH[src][lane];
                        R[q] = __fmaf_rn(dv, dhH[src][lane], R[q]);
                    }
                    __syncwarp();
                }
                while (bal1) {
                    const int src = __ffs(bal1) - 1; bal1 &= bal1 - 1;
                    const float dv = __shfl_sync(0xFFFFFFFFu, dv1, src);
                    const int k = src + 32;
                    if (lane < cntH[k]) {
                        const int q = qH[k][lane];
                        R[q] = __fmaf_rn(dv, dhH[k][lane], R[q]);
                    }
                    __syncwarp();
                }
            }
        }
        if (doscan) {
            __syncwarp();
            float carry = 0.f;
            float4* r4 = (float4*)R;
            #pragma unroll
            for (int m = 0; m < 4; ++m) {
                float4 c = r4[m * 32 + lane];
                r4[m * 32 + lane] = make_float4(0.f, 0.f, 0.f, 0.f);  // clear for next row
                c.y += c.x; c.z += c.y; c.w += c.z;
                const float t = c.w;
                float incl = t;
                #pragma unroll
                for (int d = 1; d < 32; d <<= 1) {
                    const float s = __shfl_up_sync(0xFFFFFFFFu, incl, d);
                    if (lane >= d) incl += s;
                }
                const float add = incl - t + carry;
                O[4 * m + 0] += c.x + add;
                O[4 * m + 1] += c.y + add;
                O[4 * m + 2] += c.z + add;
                O[4 * m + 3] += c.w + add;
                carry += __shfl_sync(0xFFFFFFFFu, incl, 31);
            }
            __syncwarp();
        }
        // coalesced row store (always)
        orow[lane +  0] = make_float4(O[0],  O[1],  O[2],  O[3]);
        orow[lane + 32] = make_float4(O[4],  O[5],  O[6],  O[7]);
        orow[lane + 64] = make_float4(O[8],  O[9],  O[10], O[11]);
        orow[lane + 96] = make_float4(O[12], O[13], O[14], O[15]);
        orow += 128;
    }
}

extern "C" void kernel_launch(void* const* d_in, const int* in_sizes, int n_in,
                              void* d_out, int out_size)
{
    const float* iv0 = (const float*)d_in[0];   // intervals00: (256, 32, 2) f32
    const float* iv1 = (const float*)d_in[1];   // intervals01: (256, 32, 2) f32
    float* out = (float*)d_out;                 // (256, 2, 512, 512) f32
    (void)in_sizes; (void)n_in; (void)out_size;
    raster_kernel<<<512, NTHREADS>>>(iv0, iv1, out);
}

// round 6
// speedup vs baseline: 4.1520x; 1.1473x over previous
#include <cuda_runtime.h>
#include <stdint.h>

// RasterTriangle_46566035423850 — fully sparse 2D formulation.
// out[p,q] = sum_k v(p,k) * H_k[q].  Both v(.,k) over p and H(.,k) over q are
// piecewise constant except within one-pixel ramps => per-k diff lists dv (over p)
// and dh (over q) each have <= ~7 entries, found by evaluating the EXACT reference
// fp32 formula inside analytically-located windows (+/-2 sample guard).
// Per warp: base row p0 built by scatter+scan, then rows advance incrementally:
//   out[p,:] = out[p-1,:] + prefix_q( sum_{k: dv at p} dv * dH_k )   (usually zero).
// R6: 1024 CTAs (half-image each, 32-row warp segments) for load balance;
//     streaming (evict-first) output stores.

#define NTHREADS 256
#define NW 8
#define SEG 32    // rows per warp
#define MAXD 12   // max diffs per k per dim (true bound ~7)

__global__ void __launch_bounds__(NTHREADS)
raster_kernel(const float* __restrict__ iv0,
              const float* __restrict__ iv1,
              float* __restrict__ out)
{
    const double PI_D   = 3.141592653589793238462643383279502884;
    const double SIDE_D = (PI_D * 0.5) / 512.0;
    const float  S      = (float)SIDE_D;
    const float  STRIPF = (float)(PI_D * 0.5);
    const float  STOPF  = (float)(PI_D * 0.5 - SIDE_D);
    const float  stepx  = __fdiv_rn(STOPF, 511.0f);
    const float  stepy  = __fdiv_rn(-STOPF, 511.0f);
    const float  invA   = (float)(1.0 / (SIDE_D * SIDE_D));

    __shared__ __align__(16) float xs[64], ys[64];
    __shared__ __align__(16) float dhH[64][MAXD];
    __shared__ __align__(16) float dvV[64][MAXD];
    __shared__ __align__(16) short qH[64][MAXD];
    __shared__ __align__(16) short pV[64][MAXD];
    __shared__ int   cntH[64], cntV[64];
    __shared__ __align__(16) float Rbuf[NW][512];
    __shared__ __align__(16) float vbuf[NW][64];

    const int tid     = threadIdx.x;
    const int imgslot = blockIdx.x >> 1;   // 0..511 = b*2 + img
    const int half    = blockIdx.x & 1;    // which 256-row half
    const int img     = imgslot & 1;
    const int b       = imgslot >> 1;
    const int K       = img ? 32 : 64;

    // zero R scratch (8 warps x 512 floats)
    {
        float4* r4 = (float4*)&Rbuf[0][0];
        #pragma unroll
        for (int i = 0; i < 4; ++i)
            r4[tid * 4 + i] = make_float4(0.f, 0.f, 0.f, 0.f);
    }
    // load interval endpoints (reference's concat semantics)
    if (tid < 32) {
        const float2 ab = ((const float2*)iv0)[b * 32 + tid];
        xs[tid] = ab.x;  ys[tid] = ab.y;                 // (a0, b0)
    } else if (tid < 64 && img == 0) {
        const float2 ab = ((const float2*)iv1)[b * 32 + (tid - 32)];
        xs[tid] = __fsub_rn(ab.y, STRIPF);               // b1 - STRIP
        ys[tid] = ab.x;                                  // a1
    }
    __syncthreads();

    // ---- Phase 1: per-(k, dim) windowed diff extraction ----
    if (tid < 2 * K) {
        const int k   = tid >> 1;
        const int dim = tid & 1;     // 0 = horizontal(q), 1 = vertical(p)
        const float x = xs[k], y = ys[k];

        // analytic ramp windows (float sample coords)
        float w1lo, w1hi, w2lo, w2hi; int has2;
        if (dim == 0) {
            w1lo = __fdiv_rn(__fsub_rn(x, S), stepx);  w1hi = __fdiv_rn(x, stepx);
            w2lo = __fdiv_rn(__fsub_rn(y, S), stepx);  w2hi = __fdiv_rn(y, stepx);
            has2 = (img == 0);
        } else {
            w1lo = __fdiv_rn(__fsub_rn(STOPF, y), stepx);
            w1hi = __fdiv_rn(__fadd_rn(__fsub_rn(STOPF, y), S), stepx);
            const float t = __fsub_rn(__fsub_rn(STOPF, x), STRIPF);
            w2lo = __fdiv_rn(t, stepx);
            w2hi = __fdiv_rn(__fadd_rn(t, S), stepx);
            has2 = (img == 0);
        }

        int aLo = 0, aHi = -1, bLo = 0, bHi = -1;
        {
            const int lo = (int)floorf(w1lo) - 2, hi = (int)ceilf(w1hi) + 2;
            if (lo <= 511) { aLo = max(lo, 0); aHi = min(511, max(hi, 0)); }
        }
        if (has2) {
            const int lo = (int)floorf(w2lo) - 2, hi = (int)ceilf(w2hi) + 2;
            if (lo <= 511) { bLo = max(lo, 0); bHi = min(511, max(hi, 0)); }
        }
        if (aHi < aLo) { aLo = bLo; aHi = bHi; bHi = -1; }      // A empty -> use B
        if (bHi >= bLo) {                                        // both nonempty
            if (bLo < aLo) { int t;                              // order by lo
                t = aLo; aLo = bLo; bLo = t;  t = aHi; aHi = bHi; bHi = t; }
            if (bLo <= aHi + 1) { aHi = max(aHi, bHi); bHi = -1; }   // merge
        }

        short* qq = dim ? pV[k] : qH[k];
        float* dd = dim ? dvV[k] : dhH[k];
        int cnt = 0;
        #pragma unroll 1
        for (int sp = 0; sp < 2; ++sp) {
            const int lo = sp ? bLo : aLo, hi = sp ? bHi : aHi;
            if (hi < lo) continue;
            float prev = 0.f;
            for (int t = (lo == 0 ? 0 : lo - 1); t <= hi; ++t) {
                float f;
                if (dim == 0) {
                    const float px = __fmul_rn((float)t, stepx);
                    const float A  = __fsub_rn(__fadd_rn(px, S), x);
                    const float m  = img ? A : fminf(A, __fsub_rn(y, px));
                    f = fmaxf(fminf(S, m), 0.f);
                } else {
                    const float py = __fadd_rn(STOPF, __fmul_rn((float)t, stepy));
                    float m;
                    if (img) m = __fsub_rn(y, py);
                    else m = fminf(__fsub_rn(__fadd_rn(py, S), y),
                                   __fsub_rn(__fadd_rn(x, STRIPF), py));
                    f = fmaxf(fminf(S, m), 0.f);
                }
                if (t >= lo && f != prev && cnt < MAXD) {
                    qq[cnt] = (short)t;
                    dd[cnt] = dim ? __fmul_rn(__fsub_rn(f, prev), invA)
                                  : __fsub_rn(f, prev);
                    ++cnt;
                }
                prev = f;
            }
        }
        (dim ? cntV : cntH)[k] = cnt;
    }
    __syncthreads();

    // ---- Phase 2: per-warp segment of SEG rows ----
    const int warp = tid >> 5;
    const int lane = tid & 31;
    const int p0   = (half << 8) + warp * SEG;
    float* const R = Rbuf[warp];

    // v(p0, k) * invA  (closed form, identical ops to reference)
    {
        const float py = __fadd_rn(STOPF, __fmul_rn((float)p0, stepy));
        {
            const float x = xs[lane], y = ys[lane];
            float m;
            if (img) m = __fsub_rn(y, py);
            else m = fminf(__fsub_rn(__fadd_rn(py, S), y),
                           __fsub_rn(__fadd_rn(x, STRIPF), py));
            vbuf[warp][lane] = fmaxf(fminf(S, m), 0.f) * invA;
        }
        if (!img) {
            const float x = xs[lane + 32], y = ys[lane + 32];
            const float m = fminf(__fsub_rn(__fadd_rn(py, S), y),
                                  __fsub_rn(__fadd_rn(x, STRIPF), py));
            vbuf[warp][lane + 32] = fmaxf(fminf(S, m), 0.f) * invA;
        }
    }
    __syncwarp();

    // base row: R[q] += v(p0,k) * dh  (lane j handles entry j of k; serial over k)
    for (int k = 0; k < K; ++k) {
        const float v = vbuf[warp][k];     // broadcast
        if (v != 0.f) {
            if (lane < cntH[k]) {
                const int q = qH[k][lane];
                R[q] = __fmaf_rn(v, dhH[k][lane], R[q]);
            }
            __syncwarp();
        }
    }

    // dv cursors: lane owns k0 = lane (and k1 = lane+32 for hf)
    const int k0 = lane, k1 = lane + 32;
    const int c0 = cntV[k0];
    const int c1 = (img == 0) ? cntV[k1] : 0;
    int cur0 = 0; while (cur0 < c0 && pV[k0][cur0] <= p0) ++cur0;
    int cur1 = 0; while (cur1 < c1 && pV[k1][cur1] <= p0) ++cur1;
    int np0 = (cur0 < c0) ? pV[k0][cur0] : (1 << 30);
    int np1 = (cur1 < c1) ? pV[k1][cur1] : (1 << 30);

    float O[16];
    #pragma unroll
    for (int i = 0; i < 16; ++i) O[i] = 0.f;

    float* orow = out + ((size_t)imgslot << 18) + ((size_t)p0 << 9);

    for (int p = p0; p < p0 + SEG; ++p) {
        bool doscan = (p == p0);
        if (p > p0) {
            const bool m0 = (np0 == p), m1 = (np1 == p);
            unsigned bal0 = __ballot_sync(0xFFFFFFFFu, m0);
            unsigned bal1 = __ballot_sync(0xFFFFFFFFu, m1);
            float dv0 = 0.f, dv1 = 0.f;
            if (m0) { dv0 = dvV[k0][cur0]; ++cur0;
                      np0 = (cur0 < c0) ? pV[k0][cur0] : (1 << 30); }
            if (m1) { dv1 = dvV[k1][cur1]; ++cur1;
                      np1 = (cur1 < c1) ? pV[k1][cur1] : (1 << 30); }
            if (bal0 | bal1) {
                doscan = true;
                while (bal0) {
                    const int src = __ffs(bal0) - 1; bal0 &= bal0 - 1;
                    const float dv = __shfl_sync(0xFFFFFFFFu, dv0, src);
                    if (lane < cntH[src]) {
                        const int q = qH[src][lane];
                        R[q] = __fmaf_rn(dv, dhH[src][lane], R[q]);
                    }
                    __syncwarp();
                }
                while (bal1) {
                    const int src = __ffs(bal1) - 1; bal1 &= bal1 - 1;
                    const float dv = __shfl_sync(0xFFFFFFFFu, dv1, src);
                    const int k = src + 32;
                    if (lane < cntH[k]) {
                        const int q = qH[k][lane];
                        R[q] = __fmaf_rn(dv, dhH[k][lane], R[q]);
                    }
                    __syncwarp();
                }
            }
        }
        if (doscan) {
            __syncwarp();
            float carry = 0.f;
            float4* r4 = (float4*)R;
            #pragma unroll
            for (int m = 0; m < 4; ++m) {
                float4 c = r4[m * 32 + lane];
                r4[m * 32 + lane] = make_float4(0.f, 0.f, 0.f, 0.f);  // clear for next row
                c.y += c.x; c.z += c.y; c.w += c.z;
                const float t = c.w;
                float incl = t;
                #pragma unroll
                for (int d = 1; d < 32; d <<= 1) {
                    const float s = __shfl_up_sync(0xFFFFFFFFu, incl, d);
                    if (lane >= d) incl += s;
                }
                const float add = incl - t + carry;
                O[4 * m + 0] += c.x + add;
                O[4 * m + 1] += c.y + add;
                O[4 * m + 2] += c.z + add;
                O[4 * m + 3] += c.w + add;
                carry += __shfl_sync(0xFFFFFFFFu, incl, 31);
            }
            __syncwarp();
        }
        // coalesced streaming row store (always)
        __stcs((float4*)(orow) + lane +  0, make_float4(O[0],  O[1],  O[2],  O[3]));
        __stcs((float4*)(orow) + lane + 32, make_float4(O[4],  O[5],  O[6],  O[7]));
        __stcs((float4*)(orow) + lane + 64, make_float4(O[8],  O[9],  O[10], O[11]));
        __stcs((float4*)(orow) + lane + 96, make_float4(O[12], O[13], O[14], O[15]));
        orow += 512;
    }
}

extern "C" void kernel_launch(void* const* d_in, const int* in_sizes, int n_in,
                              void* d_out, int out_size)
{
    const float* iv0 = (const float*)d_in[0];   // intervals00: (256, 32, 2) f32
    const float* iv1 = (const float*)d_in[1];   // intervals01: (256, 32, 2) f32
    float* out = (float*)d_out;                 // (256, 2, 512, 512) f32
    (void)in_sizes; (void)n_in; (void)out_size;
    raster_kernel<<<1024, NTHREADS>>>(iv0, iv1, out);
}